// round 1
// baseline (speedup 1.0000x reference)
#include <cuda_runtime.h>
#include <cuda_bf16.h>
#include <math.h>

// ---------------- problem constants ----------------
#define BB    32
#define HH    28
#define WW    28
#define CC    192
#define HEADS 6
#define HD    32
#define KW    3
#define K2    9
#define NTOK  (BB*HH*WW)          // 25088
#define HID   576
#define ACOLS (K2*K2*HEADS)       // 486
#define SCALE 0.17677669529663687f  // 32^-0.5
#define EPSLN 1e-5f

// ---------------- scratch (static device globals; no allocs) ----------------
__device__ float g_ln1[(size_t)NTOK*CC];
__device__ float g_v  [(size_t)NTOK*CC];
__device__ float g_a  [(size_t)NTOK*ACOLS];
__device__ float g_o  [(size_t)NTOK*K2*CC];
__device__ float g_tmp[(size_t)NTOK*CC];
__device__ float g_x2 [(size_t)NTOK*CC];
__device__ float g_ln2[(size_t)NTOK*CC];
__device__ float g_h1 [(size_t)NTOK*HID];

// ---------------- LayerNorm: one warp per token (C=192 = 6*32) ----------------
__global__ void ln_kernel(const float* __restrict__ x,
                          const float* __restrict__ g,
                          const float* __restrict__ b,
                          float* __restrict__ out)
{
    int warp = (blockIdx.x * blockDim.x + threadIdx.x) >> 5;
    int lane = threadIdx.x & 31;
    if (warp >= NTOK) return;
    const float* row = x + (size_t)warp * CC;
    float vals[6];
    float s = 0.f;
    #pragma unroll
    for (int i = 0; i < 6; i++) { vals[i] = row[lane + 32*i]; s += vals[i]; }
    #pragma unroll
    for (int o = 16; o > 0; o >>= 1) s += __shfl_xor_sync(0xffffffffu, s, o);
    float mean = s * (1.f/CC);
    float vs = 0.f;
    #pragma unroll
    for (int i = 0; i < 6; i++) { float d = vals[i]-mean; vs += d*d; }
    #pragma unroll
    for (int o = 16; o > 0; o >>= 1) vs += __shfl_xor_sync(0xffffffffu, vs, o);
    float r = rsqrtf(vs * (1.f/CC) + EPSLN);
    float* orow = out + (size_t)warp * CC;
    #pragma unroll
    for (int i = 0; i < 6; i++) {
        int c = lane + 32*i;
        orow[c] = (vals[i]-mean) * r * g[c] + b[c];
    }
}

// ---------------- SGEMM: out[N,M] = A[N,K] @ Bw[K,M] (+bias)(+gelu|+res) ----------------
// EPI: 0 = bias only (bias may be null), 1 = bias+gelu, 2 = bias+residual
template<int EPI>
__global__ void gemm_kernel(const float* __restrict__ A,
                            const float* __restrict__ Bw,
                            const float* __restrict__ bias,
                            const float* __restrict__ res,
                            float* __restrict__ out,
                            int Kd, int M)
{
    __shared__ float sA[16][64];
    __shared__ float sB[16][64];
    const int col0 = blockIdx.x * 64;
    const int row0 = blockIdx.y * 64;     // NTOK divisible by 64
    const int tid  = threadIdx.x;
    const int ty   = tid >> 4;
    const int tx   = tid & 15;

    float acc[4][4];
    #pragma unroll
    for (int i = 0; i < 4; i++)
        #pragma unroll
        for (int j = 0; j < 4; j++) acc[i][j] = 0.f;

    for (int kb = 0; kb < Kd; kb += 16) {
        #pragma unroll
        for (int i = tid; i < 1024; i += 256) {
            int r = i >> 4, kk = i & 15;
            sA[kk][r] = A[(size_t)(row0 + r) * Kd + kb + kk];
        }
        #pragma unroll
        for (int i = tid; i < 1024; i += 256) {
            int kk = i >> 6, cc = i & 63;
            int col = col0 + cc;
            sB[kk][cc] = (col < M) ? Bw[(size_t)(kb + kk) * M + col] : 0.f;
        }
        __syncthreads();
        #pragma unroll
        for (int kk = 0; kk < 16; kk++) {
            float ra[4], rb[4];
            #pragma unroll
            for (int i = 0; i < 4; i++) ra[i] = sA[kk][ty*4 + i];
            #pragma unroll
            for (int j = 0; j < 4; j++) rb[j] = sB[kk][tx*4 + j];
            #pragma unroll
            for (int i = 0; i < 4; i++)
                #pragma unroll
                for (int j = 0; j < 4; j++) acc[i][j] = fmaf(ra[i], rb[j], acc[i][j]);
        }
        __syncthreads();
    }

    #pragma unroll
    for (int i = 0; i < 4; i++) {
        int row = row0 + ty*4 + i;
        #pragma unroll
        for (int j = 0; j < 4; j++) {
            int col = col0 + tx*4 + j;
            if (col < M) {
                float v = acc[i][j];
                if (bias) v += bias[col];
                if (EPI == 1) {
                    v = 0.5f * v * (1.0f + erff(v * 0.70710678118654752f));
                } else if (EPI == 2) {
                    v += res[(size_t)row * M + col];
                }
                out[(size_t)row * M + col] = v;
            }
        }
    }
}

// ---------------- Outlook attention: one warp per (token, head) ----------------
__global__ void attn_kernel(const float* __restrict__ a,
                            const float* __restrict__ v,
                            float* __restrict__ o)
{
    __shared__ float sm[8][81];
    int warp = threadIdx.x >> 5;
    int lane = threadIdx.x & 31;
    long gw = (long)blockIdx.x * 8 + warp;      // (token, head) index
    int t    = (int)(gw / HEADS);
    int head = (int)(gw % HEADS);
    int b  = t / (HH*WW);
    int pq = t % (HH*WW);
    int p = pq / WW, q = pq % WW;

    const float* arow = a + (size_t)t * ACOLS + head * (K2*K2);
    if (lane < K2) {
        float vv[K2];
        float mx = -INFINITY;
        #pragma unroll
        for (int j = 0; j < K2; j++) { vv[j] = arow[lane*K2 + j] * SCALE; mx = fmaxf(mx, vv[j]); }
        float s = 0.f;
        #pragma unroll
        for (int j = 0; j < K2; j++) { vv[j] = expf(vv[j] - mx); s += vv[j]; }
        float inv = 1.f / s;
        #pragma unroll
        for (int j = 0; j < K2; j++) sm[warp][lane*K2 + j] = vv[j] * inv;
    }
    __syncwarp();

    // gather V window: vj[j] = v[b, p+i-1, q+jj-1, head*32+lane] (zero pad)
    float vj[K2];
    #pragma unroll
    for (int j = 0; j < K2; j++) {
        int di = j / KW, dj = j % KW;
        int pp = p + di - 1, qq = q + dj - 1;
        if (pp >= 0 && pp < HH && qq >= 0 && qq < WW) {
            size_t ts = ((size_t)(b*HH + pp) * WW + qq);
            vj[j] = v[ts * CC + head*HD + lane];
        } else {
            vj[j] = 0.f;
        }
    }
    #pragma unroll
    for (int i = 0; i < K2; i++) {
        float accv = 0.f;
        #pragma unroll
        for (int j = 0; j < K2; j++) accv = fmaf(sm[warp][i*K2 + j], vj[j], accv);
        o[((size_t)t * K2 + i) * CC + head*HD + lane] = accv;
    }
}

// ---------------- fold (gather form, no atomics) ----------------
__global__ void fold_kernel(const float* __restrict__ o, float* __restrict__ tmp)
{
    int idx = blockIdx.x * 256 + threadIdx.x;
    int c = idx % CC;
    int t = idx / CC;
    int b  = t / (HH*WW);
    int pq = t % (HH*WW);
    int p = pq / WW, q = pq % WW;
    float s = 0.f;
    #pragma unroll
    for (int i = 0; i < KW; i++) {
        int pp = p + 1 - i;
        if (pp < 0 || pp >= HH) continue;
        #pragma unroll
        for (int j = 0; j < KW; j++) {
            int qq = q + 1 - j;
            if (qq < 0 || qq >= WW) continue;
            int ts = (b*HH + pp) * WW + qq;
            s += o[((size_t)ts * K2 + (i*KW + j)) * CC + c];
        }
    }
    tmp[idx] = s;
}

// ---------------- launcher ----------------
extern "C" void kernel_launch(void* const* d_in, const int* in_sizes, int n_in,
                              void* d_out, int out_size)
{
    const float* x     = (const float*)d_in[0];
    const float* ln1_g = (const float*)d_in[1];
    const float* ln1_b = (const float*)d_in[2];
    const float* Wv    = (const float*)d_in[3];
    const float* Wa    = (const float*)d_in[4];
    const float* ba    = (const float*)d_in[5];
    const float* Wp    = (const float*)d_in[6];
    const float* bp    = (const float*)d_in[7];
    const float* ln2_g = (const float*)d_in[8];
    const float* ln2_b = (const float*)d_in[9];
    const float* W1    = (const float*)d_in[10];
    const float* b1    = (const float*)d_in[11];
    const float* W2    = (const float*)d_in[12];
    const float* b2    = (const float*)d_in[13];
    float* out = (float*)d_out;

    float *p_ln1, *p_v, *p_a, *p_o, *p_tmp, *p_x2, *p_ln2, *p_h1;
    cudaGetSymbolAddress((void**)&p_ln1, g_ln1);
    cudaGetSymbolAddress((void**)&p_v,   g_v);
    cudaGetSymbolAddress((void**)&p_a,   g_a);
    cudaGetSymbolAddress((void**)&p_o,   g_o);
    cudaGetSymbolAddress((void**)&p_tmp, g_tmp);
    cudaGetSymbolAddress((void**)&p_x2,  g_x2);
    cudaGetSymbolAddress((void**)&p_ln2, g_ln2);
    cudaGetSymbolAddress((void**)&p_h1,  g_h1);

    const int ROWB = NTOK / 64;  // 392

    // 1) ln1
    ln_kernel<<<NTOK/8, 256>>>(x, ln1_g, ln1_b, p_ln1);
    // 2) v = ln1 @ Wv
    gemm_kernel<0><<<dim3((CC+63)/64, ROWB), 256>>>(p_ln1, Wv, nullptr, nullptr, p_v, CC, CC);
    // 3) a = ln1 @ Wa + ba
    gemm_kernel<0><<<dim3((ACOLS+63)/64, ROWB), 256>>>(p_ln1, Wa, ba, nullptr, p_a, CC, ACOLS);
    // 4) attention -> o
    attn_kernel<<<(NTOK*HEADS)/8, 256>>>(p_a, p_v, p_o);
    // 5) fold -> tmp
    fold_kernel<<<(NTOK*CC)/256, 256>>>(p_o, p_tmp);
    // 6) x2 = tmp @ Wp + bp + x
    gemm_kernel<2><<<dim3((CC+63)/64, ROWB), 256>>>(p_tmp, Wp, bp, x, p_x2, CC, CC);
    // 7) ln2
    ln_kernel<<<NTOK/8, 256>>>(p_x2, ln2_g, ln2_b, p_ln2);
    // 8) h1 = gelu(ln2 @ W1 + b1)
    gemm_kernel<1><<<dim3((HID+63)/64, ROWB), 256>>>(p_ln2, W1, b1, nullptr, p_h1, CC, HID);
    // 9) out = h1 @ W2 + b2 + x2
    gemm_kernel<2><<<dim3((CC+63)/64, ROWB), 256>>>(p_h1, W2, b2, p_x2, out, HID, CC);
}

// round 2
// speedup vs baseline: 2.8285x; 2.8285x over previous
#include <cuda_runtime.h>
#include <cuda_bf16.h>
#include <math.h>

// ---------------- problem constants ----------------
#define BB    32
#define HH    28
#define WW    28
#define CC    192
#define HEADS 6
#define HD    32
#define KW    3
#define K2    9
#define NTOK  (BB*HH*WW)          // 25088
#define HID   576
#define ACOLS (K2*K2*HEADS)       // 486
#define SCALE 0.17677669529663687f
#define EPSLN 1e-5f

// ---------------- scratch (static device globals; no allocs) ----------------
__device__ float g_ln1[(size_t)NTOK*CC];
__device__ float g_v  [(size_t)NTOK*CC];
__device__ float g_a  [(size_t)NTOK*ACOLS];
__device__ float g_o  [(size_t)NTOK*K2*CC];
__device__ float g_tmp[(size_t)NTOK*CC];
__device__ float g_x2 [(size_t)NTOK*CC];
__device__ float g_ln2[(size_t)NTOK*CC];
__device__ float g_h1 [(size_t)NTOK*HID];

// ---------------- LayerNorm: one warp per token ----------------
__global__ void ln_kernel(const float* __restrict__ x,
                          const float* __restrict__ g,
                          const float* __restrict__ b,
                          float* __restrict__ out)
{
    int warp = (blockIdx.x * blockDim.x + threadIdx.x) >> 5;
    int lane = threadIdx.x & 31;
    if (warp >= NTOK) return;
    const float* row = x + (size_t)warp * CC;
    float vals[6];
    float s = 0.f;
    #pragma unroll
    for (int i = 0; i < 6; i++) { vals[i] = row[lane + 32*i]; s += vals[i]; }
    #pragma unroll
    for (int o = 16; o > 0; o >>= 1) s += __shfl_xor_sync(0xffffffffu, s, o);
    float mean = s * (1.f/CC);
    float vs = 0.f;
    #pragma unroll
    for (int i = 0; i < 6; i++) { float d = vals[i]-mean; vs += d*d; }
    #pragma unroll
    for (int o = 16; o > 0; o >>= 1) vs += __shfl_xor_sync(0xffffffffu, vs, o);
    float r = rsqrtf(vs * (1.f/CC) + EPSLN);
    float* orow = out + (size_t)warp * CC;
    #pragma unroll
    for (int i = 0; i < 6; i++) {
        int c = lane + 32*i;
        orow[c] = (vals[i]-mean) * r * g[c] + b[c];
    }
}

// ---------------- TF32 tensor-core GEMM ----------------
// out[N,M] = A[N,K] @ Bw[K,M] (+bias)(+gelu|+res)
// CTA tile 128x64x32; 8 warps (4 row x 2 col), warp tile 32x32 = 2x4 m16n8k8.
__device__ __forceinline__ unsigned f2tf32(float f) {
    unsigned u;
    asm("cvt.rna.tf32.f32 %0, %1;" : "=r"(u) : "f"(f));
    return u;
}

#define SA_ST 36   // 36 % 32 == 4 -> conflict-free A fragment reads
#define SB_ST 72   // 72 % 32 == 8 -> conflict-free B fragment reads

template<int EPI>
__global__ __launch_bounds__(256, 2)
void gemm_tf32_kernel(const float* __restrict__ A,
                      const float* __restrict__ Bw,
                      const float* __restrict__ bias,
                      const float* __restrict__ res,
                      float* __restrict__ out,
                      int Kd, int M)
{
    __shared__ unsigned sA[128*SA_ST];
    __shared__ unsigned sB[32*SB_ST];

    const int tid  = threadIdx.x;
    const int lane = tid & 31;
    const int w    = tid >> 5;
    const int wr   = w & 3;        // warp row group (32 rows)
    const int wc   = w >> 2;       // warp col group (32 cols)
    const int gid  = lane >> 2;    // 0..7
    const int tig  = lane & 3;     // 0..3
    const int row0 = blockIdx.y * 128;
    const int col0 = blockIdx.x * 64;

    float acc[2][4][4];
    #pragma unroll
    for (int mt = 0; mt < 2; mt++)
        #pragma unroll
        for (int nt = 0; nt < 4; nt++)
            #pragma unroll
            for (int i = 0; i < 4; i++) acc[mt][nt][i] = 0.f;

    for (int kb = 0; kb < Kd; kb += 32) {
        // A: 128 rows x 32 k, float4 loads (rows and K always divisible)
        #pragma unroll
        for (int i = 0; i < 4; i++) {
            int f = tid + 256*i;
            int r = f >> 3, kq = (f & 7) * 4;
            float4 v4 = *(const float4*)&A[(size_t)(row0 + r) * Kd + kb + kq];
            unsigned* dst = &sA[r*SA_ST + kq];
            dst[0] = f2tf32(v4.x); dst[1] = f2tf32(v4.y);
            dst[2] = f2tf32(v4.z); dst[3] = f2tf32(v4.w);
        }
        // B: 32 k x 64 cols, scalar guarded loads
        #pragma unroll
        for (int i = 0; i < 8; i++) {
            int f = tid + 256*i;
            int kr = f >> 6, c = f & 63;
            int col = col0 + c;
            float bv = (col < M) ? Bw[(size_t)(kb + kr) * M + col] : 0.f;
            sB[kr*SB_ST + c] = f2tf32(bv);
        }
        __syncthreads();

        #pragma unroll
        for (int ks = 0; ks < 4; ks++) {
            const int k0 = ks * 8;
            unsigned af[2][4];
            #pragma unroll
            for (int mt = 0; mt < 2; mt++) {
                int r = wr*32 + mt*16 + gid;
                af[mt][0] = sA[ r     *SA_ST + k0 + tig    ];
                af[mt][1] = sA[(r + 8)*SA_ST + k0 + tig    ];
                af[mt][2] = sA[ r     *SA_ST + k0 + tig + 4];
                af[mt][3] = sA[(r + 8)*SA_ST + k0 + tig + 4];
            }
            unsigned bf[4][2];
            #pragma unroll
            for (int nt = 0; nt < 4; nt++) {
                int c = wc*32 + nt*8 + gid;
                bf[nt][0] = sB[(k0 + tig    )*SB_ST + c];
                bf[nt][1] = sB[(k0 + tig + 4)*SB_ST + c];
            }
            #pragma unroll
            for (int mt = 0; mt < 2; mt++)
                #pragma unroll
                for (int nt = 0; nt < 4; nt++) {
                    asm volatile(
                      "mma.sync.aligned.m16n8k8.row.col.f32.tf32.tf32.f32 "
                      "{%0,%1,%2,%3},{%4,%5,%6,%7},{%8,%9},{%0,%1,%2,%3};"
                      : "+f"(acc[mt][nt][0]), "+f"(acc[mt][nt][1]),
                        "+f"(acc[mt][nt][2]), "+f"(acc[mt][nt][3])
                      : "r"(af[mt][0]), "r"(af[mt][1]),
                        "r"(af[mt][2]), "r"(af[mt][3]),
                        "r"(bf[nt][0]), "r"(bf[nt][1]));
                }
        }
        __syncthreads();
    }

    // epilogue
    #pragma unroll
    for (int mt = 0; mt < 2; mt++) {
        #pragma unroll
        for (int nt = 0; nt < 4; nt++) {
            int r  = row0 + wr*32 + mt*16 + gid;
            int cb = col0 + wc*32 + nt*8 + tig*2;
            #pragma unroll
            for (int i = 0; i < 4; i++) {
                int row = r + (i >> 1) * 8;
                int col = cb + (i & 1);
                if (col < M) {
                    float v = acc[mt][nt][i];
                    if (bias) v += bias[col];
                    if (EPI == 1) {
                        v = 0.5f * v * (1.0f + erff(v * 0.70710678118654752f));
                    } else if (EPI == 2) {
                        v += res[(size_t)row * M + col];
                    }
                    out[(size_t)row * M + col] = v;
                }
            }
        }
    }
}

// ---------------- Outlook attention: one warp per (token, head) ----------------
__global__ void attn_kernel(const float* __restrict__ a,
                            const float* __restrict__ v,
                            float* __restrict__ o)
{
    __shared__ float sm[8][81];
    int warp = threadIdx.x >> 5;
    int lane = threadIdx.x & 31;
    long gw = (long)blockIdx.x * 8 + warp;
    int t    = (int)(gw / HEADS);
    int head = (int)(gw % HEADS);
    int b  = t / (HH*WW);
    int pq = t % (HH*WW);
    int p = pq / WW, q = pq % WW;

    const float* arow = a + (size_t)t * ACOLS + head * (K2*K2);
    if (lane < K2) {
        float vv[K2];
        float mx = -INFINITY;
        #pragma unroll
        for (int j = 0; j < K2; j++) { vv[j] = arow[lane*K2 + j] * SCALE; mx = fmaxf(mx, vv[j]); }
        float s = 0.f;
        #pragma unroll
        for (int j = 0; j < K2; j++) { vv[j] = expf(vv[j] - mx); s += vv[j]; }
        float inv = 1.f / s;
        #pragma unroll
        for (int j = 0; j < K2; j++) sm[warp][lane*K2 + j] = vv[j] * inv;
    }
    __syncwarp();

    float vj[K2];
    #pragma unroll
    for (int j = 0; j < K2; j++) {
        int di = j / KW, dj = j % KW;
        int pp = p + di - 1, qq = q + dj - 1;
        if (pp >= 0 && pp < HH && qq >= 0 && qq < WW) {
            size_t ts = ((size_t)(b*HH + pp) * WW + qq);
            vj[j] = v[ts * CC + head*HD + lane];
        } else {
            vj[j] = 0.f;
        }
    }
    #pragma unroll
    for (int i = 0; i < K2; i++) {
        float accv = 0.f;
        #pragma unroll
        for (int j = 0; j < K2; j++) accv = fmaf(sm[warp][i*K2 + j], vj[j], accv);
        o[((size_t)t * K2 + i) * CC + head*HD + lane] = accv;
    }
}

// ---------------- fold (gather form, no atomics) ----------------
__global__ void fold_kernel(const float* __restrict__ o, float* __restrict__ tmp)
{
    int idx = blockIdx.x * 256 + threadIdx.x;
    int c = idx % CC;
    int t = idx / CC;
    int b  = t / (HH*WW);
    int pq = t % (HH*WW);
    int p = pq / WW, q = pq % WW;
    float s = 0.f;
    #pragma unroll
    for (int i = 0; i < KW; i++) {
        int pp = p + 1 - i;
        if (pp < 0 || pp >= HH) continue;
        #pragma unroll
        for (int j = 0; j < KW; j++) {
            int qq = q + 1 - j;
            if (qq < 0 || qq >= WW) continue;
            int ts = (b*HH + pp) * WW + qq;
            s += o[((size_t)ts * K2 + (i*KW + j)) * CC + c];
        }
    }
    tmp[idx] = s;
}

// ---------------- launcher ----------------
extern "C" void kernel_launch(void* const* d_in, const int* in_sizes, int n_in,
                              void* d_out, int out_size)
{
    const float* x     = (const float*)d_in[0];
    const float* ln1_g = (const float*)d_in[1];
    const float* ln1_b = (const float*)d_in[2];
    const float* Wv    = (const float*)d_in[3];
    const float* Wa    = (const float*)d_in[4];
    const float* ba    = (const float*)d_in[5];
    const float* Wp    = (const float*)d_in[6];
    const float* bp    = (const float*)d_in[7];
    const float* ln2_g = (const float*)d_in[8];
    const float* ln2_b = (const float*)d_in[9];
    const float* W1    = (const float*)d_in[10];
    const float* b1    = (const float*)d_in[11];
    const float* W2    = (const float*)d_in[12];
    const float* b2    = (const float*)d_in[13];
    float* out = (float*)d_out;

    float *p_ln1, *p_v, *p_a, *p_o, *p_tmp, *p_x2, *p_ln2, *p_h1;
    cudaGetSymbolAddress((void**)&p_ln1, g_ln1);
    cudaGetSymbolAddress((void**)&p_v,   g_v);
    cudaGetSymbolAddress((void**)&p_a,   g_a);
    cudaGetSymbolAddress((void**)&p_o,   g_o);
    cudaGetSymbolAddress((void**)&p_tmp, g_tmp);
    cudaGetSymbolAddress((void**)&p_x2,  g_x2);
    cudaGetSymbolAddress((void**)&p_ln2, g_ln2);
    cudaGetSymbolAddress((void**)&p_h1,  g_h1);

    const int RB = NTOK / 128;   // 196

    ln_kernel<<<NTOK/8, 256>>>(x, ln1_g, ln1_b, p_ln1);
    gemm_tf32_kernel<0><<<dim3((CC+63)/64, RB), 256>>>(p_ln1, Wv, nullptr, nullptr, p_v, CC, CC);
    gemm_tf32_kernel<0><<<dim3((ACOLS+63)/64, RB), 256>>>(p_ln1, Wa, ba, nullptr, p_a, CC, ACOLS);
    attn_kernel<<<(NTOK*HEADS)/8, 256>>>(p_a, p_v, p_o);
    fold_kernel<<<(NTOK*CC)/256, 256>>>(p_o, p_tmp);
    gemm_tf32_kernel<2><<<dim3((CC+63)/64, RB), 256>>>(p_tmp, Wp, bp, x, p_x2, CC, CC);
    ln_kernel<<<NTOK/8, 256>>>(p_x2, ln2_g, ln2_b, p_ln2);
    gemm_tf32_kernel<1><<<dim3((HID+63)/64, RB), 256>>>(p_ln2, W1, b1, nullptr, p_h1, CC, HID);
    gemm_tf32_kernel<2><<<dim3((CC+63)/64, RB), 256>>>(p_h1, W2, b2, p_x2, out, HID, CC);
}

// round 4
// speedup vs baseline: 2.8322x; 1.0013x over previous
#include <cuda_runtime.h>
#include <cuda_bf16.h>
#include <math.h>

// ---------------- problem constants ----------------
#define BB    32
#define HH    28
#define WW    28
#define CC    192
#define HEADS 6
#define HD    32
#define KW    3
#define K2    9
#define NTOK  (BB*HH*WW)          // 25088
#define HID   576
#define ACOLS (K2*K2*HEADS)       // 486
#define SCALE 0.17677669529663687f
#define EPSLN 1e-5f

// ---------------- scratch (static device globals; no allocs) ----------------
__device__ float g_ln1[(size_t)NTOK*CC];
__device__ float g_v  [(size_t)NTOK*CC];
__device__ float g_a  [(size_t)NTOK*ACOLS];
__device__ float g_tmp[(size_t)NTOK*CC];
__device__ float g_x2 [(size_t)NTOK*CC];
__device__ float g_ln2[(size_t)NTOK*CC];
__device__ float g_h1 [(size_t)NTOK*HID];

// ---------------- LayerNorm: one warp per token ----------------
__global__ void ln_kernel(const float* __restrict__ x,
                          const float* __restrict__ g,
                          const float* __restrict__ b,
                          float* __restrict__ out)
{
    int warp = (blockIdx.x * blockDim.x + threadIdx.x) >> 5;
    int lane = threadIdx.x & 31;
    if (warp >= NTOK) return;
    const float* row = x + (size_t)warp * CC;
    float vals[6];
    float s = 0.f;
    #pragma unroll
    for (int i = 0; i < 6; i++) { vals[i] = row[lane + 32*i]; s += vals[i]; }
    #pragma unroll
    for (int o = 16; o > 0; o >>= 1) s += __shfl_xor_sync(0xffffffffu, s, o);
    float mean = s * (1.f/CC);
    float vs = 0.f;
    #pragma unroll
    for (int i = 0; i < 6; i++) { float d = vals[i]-mean; vs += d*d; }
    #pragma unroll
    for (int o = 16; o > 0; o >>= 1) vs += __shfl_xor_sync(0xffffffffu, vs, o);
    float r = rsqrtf(vs * (1.f/CC) + EPSLN);
    float* orow = out + (size_t)warp * CC;
    #pragma unroll
    for (int i = 0; i < 6; i++) {
        int c = lane + 32*i;
        orow[c] = (vals[i]-mean) * r * g[c] + b[c];
    }
}

// ---------------- TF32 tensor-core GEMM (double-buffered) ----------------
__device__ __forceinline__ unsigned f2tf32(float f) {
    unsigned u;
    asm("cvt.rna.tf32.f32 %0, %1;" : "=r"(u) : "f"(f));
    return u;
}

#define SA_ST 36   // 36 % 32 == 4 -> conflict-free A fragment reads
#define SB_ST 72   // >= 64 cols, 72 % 32 == 8 -> conflict-free B fragment reads
#define SA_SZ (128*SA_ST)
#define SB_SZ (32*SB_ST)
#define GEMM_SMEM ((2*SA_SZ + 2*SB_SZ)*4)   // 55296 bytes

template<int EPI>
__global__ __launch_bounds__(256, 2)
void gemm_tf32_kernel(const float* __restrict__ A,
                      const float* __restrict__ Bw,
                      const float* __restrict__ bias,
                      const float* __restrict__ res,
                      float* __restrict__ out,
                      int Kd, int M)
{
    extern __shared__ unsigned smem[];
    unsigned* sA = smem;             // 2 buffers of 128 x SA_ST
    unsigned* sB = smem + 2*SA_SZ;   // 2 buffers of 32 x SB_ST

    const int tid  = threadIdx.x;
    const int lane = tid & 31;
    const int w    = tid >> 5;
    const int wr   = w & 3;
    const int wc   = w >> 2;
    const int gid  = lane >> 2;
    const int tig  = lane & 3;
    const int row0 = blockIdx.y * 128;
    const int col0 = blockIdx.x * 64;

    float acc[2][4][4];
    #pragma unroll
    for (int mt = 0; mt < 2; mt++)
        #pragma unroll
        for (int nt = 0; nt < 4; nt++)
            #pragma unroll
            for (int i = 0; i < 4; i++) acc[mt][nt][i] = 0.f;

    float4 aReg[4];
    float  bReg[8];

    const int nk = Kd / 32;

    // prologue: load k-block 0
    #pragma unroll
    for (int i = 0; i < 4; i++) {
        int f = tid + 256*i;
        int r = f >> 3, kq = (f & 7) * 4;
        aReg[i] = *(const float4*)&A[(size_t)(row0 + r) * Kd + kq];
    }
    #pragma unroll
    for (int i = 0; i < 8; i++) {
        int f = tid + 256*i;
        int kr = f >> 6, c = f & 63;
        int col = col0 + c;
        bReg[i] = (col < M) ? Bw[(size_t)kr * M + col] : 0.f;
    }
    #pragma unroll
    for (int i = 0; i < 4; i++) {
        int f = tid + 256*i;
        int r = f >> 3, kq = (f & 7) * 4;
        unsigned* dst = &sA[r*SA_ST + kq];
        dst[0] = f2tf32(aReg[i].x); dst[1] = f2tf32(aReg[i].y);
        dst[2] = f2tf32(aReg[i].z); dst[3] = f2tf32(aReg[i].w);
    }
    #pragma unroll
    for (int i = 0; i < 8; i++) {
        int f = tid + 256*i;
        int kr = f >> 6, c = f & 63;
        sB[kr*SB_ST + c] = f2tf32(bReg[i]);
    }
    __syncthreads();

    for (int it = 0; it < nk; it++) {
        const int buf = it & 1;
        const bool more = (it + 1 < nk);
        if (more) {
            int kb = (it + 1) * 32;
            #pragma unroll
            for (int i = 0; i < 4; i++) {
                int f = tid + 256*i;
                int r = f >> 3, kq = (f & 7) * 4;
                aReg[i] = *(const float4*)&A[(size_t)(row0 + r) * Kd + kb + kq];
            }
            #pragma unroll
            for (int i = 0; i < 8; i++) {
                int f = tid + 256*i;
                int kr = f >> 6, c = f & 63;
                int col = col0 + c;
                bReg[i] = (col < M) ? Bw[(size_t)(kb + kr) * M + col] : 0.f;
            }
        }
        const unsigned* cA = sA + buf*SA_SZ;
        const unsigned* cB = sB + buf*SB_SZ;
        #pragma unroll
        for (int ks = 0; ks < 4; ks++) {
            const int k0 = ks * 8;
            unsigned af[2][4];
            #pragma unroll
            for (int mt = 0; mt < 2; mt++) {
                int r = wr*32 + mt*16 + gid;
                af[mt][0] = cA[ r     *SA_ST + k0 + tig    ];
                af[mt][1] = cA[(r + 8)*SA_ST + k0 + tig    ];
                af[mt][2] = cA[ r     *SA_ST + k0 + tig + 4];
                af[mt][3] = cA[(r + 8)*SA_ST + k0 + tig + 4];
            }
            unsigned bf[4][2];
            #pragma unroll
            for (int nt = 0; nt < 4; nt++) {
                int c = wc*32 + nt*8 + gid;
                bf[nt][0] = cB[(k0 + tig    )*SB_ST + c];
                bf[nt][1] = cB[(k0 + tig + 4)*SB_ST + c];
            }
            #pragma unroll
            for (int mt = 0; mt < 2; mt++)
                #pragma unroll
                for (int nt = 0; nt < 4; nt++) {
                    asm volatile(
                      "mma.sync.aligned.m16n8k8.row.col.f32.tf32.tf32.f32 "
                      "{%0,%1,%2,%3},{%4,%5,%6,%7},{%8,%9},{%0,%1,%2,%3};"
                      : "+f"(acc[mt][nt][0]), "+f"(acc[mt][nt][1]),
                        "+f"(acc[mt][nt][2]), "+f"(acc[mt][nt][3])
                      : "r"(af[mt][0]), "r"(af[mt][1]),
                        "r"(af[mt][2]), "r"(af[mt][3]),
                        "r"(bf[nt][0]), "r"(bf[nt][1]));
                }
        }
        if (more) {
            unsigned* nA = sA + (buf^1)*SA_SZ;
            unsigned* nB = sB + (buf^1)*SB_SZ;
            #pragma unroll
            for (int i = 0; i < 4; i++) {
                int f = tid + 256*i;
                int r = f >> 3, kq = (f & 7) * 4;
                unsigned* dst = &nA[r*SA_ST + kq];
                dst[0] = f2tf32(aReg[i].x); dst[1] = f2tf32(aReg[i].y);
                dst[2] = f2tf32(aReg[i].z); dst[3] = f2tf32(aReg[i].w);
            }
            #pragma unroll
            for (int i = 0; i < 8; i++) {
                int f = tid + 256*i;
                int kr = f >> 6, c = f & 63;
                nB[kr*SB_ST + c] = f2tf32(bReg[i]);
            }
            __syncthreads();
        }
    }

    // epilogue
    #pragma unroll
    for (int mt = 0; mt < 2; mt++) {
        #pragma unroll
        for (int nt = 0; nt < 4; nt++) {
            int r  = row0 + wr*32 + mt*16 + gid;
            int cb = col0 + wc*32 + nt*8 + tig*2;
            #pragma unroll
            for (int i = 0; i < 4; i++) {
                int row = r + (i >> 1) * 8;
                int col = cb + (i & 1);
                if (col < M) {
                    float v = acc[mt][nt][i];
                    if (bias) v += bias[col];
                    if (EPI == 1) {
                        v = 0.5f * v * (1.0f + erff(v * 0.70710678118654752f));
                    } else if (EPI == 2) {
                        v += res[(size_t)row * M + col];
                    }
                    out[(size_t)row * M + col] = v;
                }
            }
        }
    }
}

// ---------------- fused outlook attention + fold (gather form) ----------------
// tmp[u,h,c] = sum_i [ts=u-(i-ctr) valid] sum_j softmax_j(a[ts,h,i,:])[j] * v[u+(j-i), h, c]
__global__ void attn_fold_kernel(const float* __restrict__ a,
                                 const float* __restrict__ v,
                                 float* __restrict__ tmp)
{
    __shared__ float sm[8][88];   // 81 used, padded
    int warp = threadIdx.x >> 5;
    int lane = threadIdx.x & 31;
    long gw = (long)blockIdx.x * 8 + warp;
    int t    = (int)(gw / HEADS);
    int head = (int)(gw % HEADS);
    int b  = t / (HH*WW);
    int pq = t % (HH*WW);
    int p = pq / WW, q = pq % WW;

    // softmax for the 9 contributing rows (lane l handles window-slot i = l)
    if (lane < K2) {
        int di = lane / KW, dj = lane % KW;
        int tp = p + 1 - di, tq = q + 1 - dj;
        if (tp >= 0 && tp < HH && tq >= 0 && tq < WW) {
            int ts = (b*HH + tp) * WW + tq;
            const float* ar = a + (size_t)ts * ACOLS + head * (K2*K2) + lane * K2;
            float vv[K2];
            float mx = -INFINITY;
            #pragma unroll
            for (int j = 0; j < K2; j++) { vv[j] = ar[j] * SCALE; mx = fmaxf(mx, vv[j]); }
            float s = 0.f;
            #pragma unroll
            for (int j = 0; j < K2; j++) { vv[j] = expf(vv[j] - mx); s += vv[j]; }
            float inv = 1.f / s;
            #pragma unroll
            for (int j = 0; j < K2; j++) sm[warp][lane*K2 + j] = vv[j] * inv;
        } else {
            #pragma unroll
            for (int j = 0; j < K2; j++) sm[warp][lane*K2 + j] = 0.f;
        }
    }
    __syncwarp();

    // load 5x5 v neighborhood for this channel (zero outside image)
    float vr[5][5];
    #pragma unroll
    for (int dp = -2; dp <= 2; dp++) {
        #pragma unroll
        for (int dq = -2; dq <= 2; dq++) {
            int vp = p + dp, vq = q + dq;
            float val = 0.f;
            if (vp >= 0 && vp < HH && vq >= 0 && vq < WW) {
                size_t ts = ((size_t)(b*HH + vp) * WW + vq);
                val = v[ts * CC + head*HD + lane];
            }
            vr[dp+2][dq+2] = val;
        }
    }

    float acc = 0.f;
    #pragma unroll
    for (int i = 0; i < K2; i++) {
        int di = i / KW, dj = i % KW;
        #pragma unroll
        for (int j = 0; j < K2; j++) {
            int ei = j / KW, ej = j % KW;
            acc = fmaf(sm[warp][i*K2 + j], vr[ei - di + 2][ej - dj + 2], acc);
        }
    }
    tmp[(size_t)t * CC + head*HD + lane] = acc;
}

// ---------------- launcher ----------------
extern "C" void kernel_launch(void* const* d_in, const int* in_sizes, int n_in,
                              void* d_out, int out_size)
{
    const float* x     = (const float*)d_in[0];
    const float* ln1_g = (const float*)d_in[1];
    const float* ln1_b = (const float*)d_in[2];
    const float* Wv    = (const float*)d_in[3];
    const float* Wa    = (const float*)d_in[4];
    const float* ba    = (const float*)d_in[5];
    const float* Wp    = (const float*)d_in[6];
    const float* bp    = (const float*)d_in[7];
    const float* ln2_g = (const float*)d_in[8];
    const float* ln2_b = (const float*)d_in[9];
    const float* W1    = (const float*)d_in[10];
    const float* b1    = (const float*)d_in[11];
    const float* W2    = (const float*)d_in[12];
    const float* b2    = (const float*)d_in[13];
    float* out = (float*)d_out;

    float *p_ln1, *p_v, *p_a, *p_tmp, *p_x2, *p_ln2, *p_h1;
    cudaGetSymbolAddress((void**)&p_ln1, g_ln1);
    cudaGetSymbolAddress((void**)&p_v,   g_v);
    cudaGetSymbolAddress((void**)&p_a,   g_a);
    cudaGetSymbolAddress((void**)&p_tmp, g_tmp);
    cudaGetSymbolAddress((void**)&p_x2,  g_x2);
    cudaGetSymbolAddress((void**)&p_ln2, g_ln2);
    cudaGetSymbolAddress((void**)&p_h1,  g_h1);

    cudaFuncSetAttribute(gemm_tf32_kernel<0>, cudaFuncAttributeMaxDynamicSharedMemorySize, GEMM_SMEM);
    cudaFuncSetAttribute(gemm_tf32_kernel<1>, cudaFuncAttributeMaxDynamicSharedMemorySize, GEMM_SMEM);
    cudaFuncSetAttribute(gemm_tf32_kernel<2>, cudaFuncAttributeMaxDynamicSharedMemorySize, GEMM_SMEM);

    const int RB = NTOK / 128;   // 196

    ln_kernel<<<NTOK/8, 256>>>(x, ln1_g, ln1_b, p_ln1);
    gemm_tf32_kernel<0><<<dim3((CC+63)/64, RB), 256, GEMM_SMEM>>>(p_ln1, Wv, nullptr, nullptr, p_v, CC, CC);
    gemm_tf32_kernel<0><<<dim3((ACOLS+63)/64, RB), 256, GEMM_SMEM>>>(p_ln1, Wa, ba, nullptr, p_a, CC, ACOLS);
    attn_fold_kernel<<<(NTOK*HEADS)/8, 256>>>(p_a, p_v, p_tmp);
    gemm_tf32_kernel<2><<<dim3((CC+63)/64, RB), 256, GEMM_SMEM>>>(p_tmp, Wp, bp, x, p_x2, CC, CC);
    ln_kernel<<<NTOK/8, 256>>>(p_x2, ln2_g, ln2_b, p_ln2);
    gemm_tf32_kernel<1><<<dim3((HID+63)/64, RB), 256, GEMM_SMEM>>>(p_ln2, W1, b1, nullptr, p_h1, CC, HID);
    gemm_tf32_kernel<2><<<dim3((CC+63)/64, RB), 256, GEMM_SMEM>>>(p_h1, W2, b2, p_x2, out, HID, CC);
}

// round 5
// speedup vs baseline: 3.8100x; 1.3452x over previous
#include <cuda_runtime.h>
#include <cuda_bf16.h>
#include <math.h>

// ---------------- problem constants ----------------
#define BB    32
#define HH    28
#define WW    28
#define CC    192
#define HEADS 6
#define HD    32
#define KW    3
#define K2    9
#define NTOK  (BB*HH*WW)          // 25088
#define HID   576
#define ACOLS (K2*K2*HEADS)       // 486
#define SCALE 0.17677669529663687f
#define EPSLN 1e-5f

// ---------------- scratch (static device globals; no allocs) ----------------
__device__ float g_ln1[(size_t)NTOK*CC];
__device__ float g_v  [(size_t)NTOK*CC];
__device__ float g_a  [(size_t)NTOK*ACOLS];
__device__ float g_tmp[(size_t)NTOK*CC];
__device__ float g_x2 [(size_t)NTOK*CC];
__device__ float g_ln2[(size_t)NTOK*CC];
__device__ float g_h1 [(size_t)NTOK*HID];

// ---------------- LayerNorm: one warp per token ----------------
__global__ void ln_kernel(const float* __restrict__ x,
                          const float* __restrict__ g,
                          const float* __restrict__ b,
                          float* __restrict__ out)
{
    int warp = (blockIdx.x * blockDim.x + threadIdx.x) >> 5;
    int lane = threadIdx.x & 31;
    if (warp >= NTOK) return;
    const float* row = x + (size_t)warp * CC;
    float vals[6];
    float s = 0.f;
    #pragma unroll
    for (int i = 0; i < 6; i++) { vals[i] = row[lane + 32*i]; s += vals[i]; }
    #pragma unroll
    for (int o = 16; o > 0; o >>= 1) s += __shfl_xor_sync(0xffffffffu, s, o);
    float mean = s * (1.f/CC);
    float vs = 0.f;
    #pragma unroll
    for (int i = 0; i < 6; i++) { float d = vals[i]-mean; vs += d*d; }
    #pragma unroll
    for (int o = 16; o > 0; o >>= 1) vs += __shfl_xor_sync(0xffffffffu, vs, o);
    float r = rsqrtf(vs * (1.f/CC) + EPSLN);
    float* orow = out + (size_t)warp * CC;
    #pragma unroll
    for (int i = 0; i < 6; i++) {
        int c = lane + 32*i;
        orow[c] = (vals[i]-mean) * r * g[c] + b[c];
    }
}

// ---------------- TF32 tensor-core GEMM (cp.async, 3-stage) ----------------
#define SA_ST 36   // 36 % 32 == 4 -> conflict-free A fragment reads
#define SB_ST 72   // >= 64 cols, 72 % 32 == 8 -> conflict-free B fragment reads
#define SA_SZ (128*SA_ST)          // words per A stage
#define SB_SZ (32*SB_ST)           // words per B stage
#define STG_WORDS (SA_SZ + SB_SZ)  // 6912 words / stage
#define GEMM_SMEM (3*STG_WORDS*4)  // 82944 bytes

__device__ __forceinline__ void cp16(unsigned dst, const void* src) {
    asm volatile("cp.async.ca.shared.global [%0], [%1], 16;" :: "r"(dst), "l"(src));
}
__device__ __forceinline__ void cp8z(unsigned dst, const void* src, int nbytes) {
    asm volatile("cp.async.ca.shared.global [%0], [%1], 8, %2;" :: "r"(dst), "l"(src), "r"(nbytes));
}
__device__ __forceinline__ void cp_commit() {
    asm volatile("cp.async.commit_group;");
}

template<int EPI>
__global__ __launch_bounds__(256, 2)
void gemm_tf32_kernel(const float* __restrict__ A,
                      const float* __restrict__ Bw,
                      const float* __restrict__ bias,
                      const float* __restrict__ res,
                      float* __restrict__ out,
                      int Kd, int M)
{
    extern __shared__ unsigned smem[];
    const unsigned smem_base = (unsigned)__cvta_generic_to_shared(smem);

    const int tid  = threadIdx.x;
    const int lane = tid & 31;
    const int w    = tid >> 5;
    const int wr   = w & 3;
    const int wc   = w >> 2;
    const int gid  = lane >> 2;
    const int tig  = lane & 3;
    const int row0 = blockIdx.y * 128;
    const int col0 = blockIdx.x * 64;

    float acc[2][4][4];
    #pragma unroll
    for (int mt = 0; mt < 2; mt++)
        #pragma unroll
        for (int nt = 0; nt < 4; nt++)
            #pragma unroll
            for (int i = 0; i < 4; i++) acc[mt][nt][i] = 0.f;

    const int nk = Kd / 32;

    // ---- async stage issue helper (inlined via lambda-like macro) ----
    auto issue_stage = [&](int s) {
        int kb = s * 32;
        unsigned base = smem_base + (unsigned)((s % 3) * STG_WORDS * 4);
        #pragma unroll
        for (int i = 0; i < 4; i++) {
            int f = tid + 256*i;
            int r = f >> 3, kq = (f & 7) * 4;
            cp16(base + (unsigned)((r*SA_ST + kq)*4),
                 &A[(size_t)(row0 + r) * Kd + kb + kq]);
        }
        unsigned bbase = base + (unsigned)(SA_SZ*4);
        #pragma unroll
        for (int i = 0; i < 4; i++) {
            int f = tid + 256*i;
            int kr = f >> 5, c2 = f & 31;
            int col = col0 + c2*2;
            int rem = M - col;
            int nb = rem >= 2 ? 8 : (rem == 1 ? 4 : 0);
            int colc = col < M - 2 ? col : M - 2;
            cp8z(bbase + (unsigned)((kr*SB_ST + c2*2)*4),
                 &Bw[(size_t)(kb + kr) * M + colc], nb);
        }
    };

    // prologue: stages 0 and 1
    issue_stage(0); cp_commit();
    if (nk > 1) { issue_stage(1); cp_commit(); }

    for (int it = 0; it < nk; it++) {
        if (it + 1 < nk) asm volatile("cp.async.wait_group 1;" ::: "memory");
        else             asm volatile("cp.async.wait_group 0;" ::: "memory");
        __syncthreads();

        const unsigned* cA = (const unsigned*)smem + (it % 3) * STG_WORDS;
        const unsigned* cB = cA + SA_SZ;
        #pragma unroll
        for (int ks = 0; ks < 4; ks++) {
            const int k0 = ks * 8;
            unsigned af[2][4];
            #pragma unroll
            for (int mt = 0; mt < 2; mt++) {
                int r = wr*32 + mt*16 + gid;
                af[mt][0] = cA[ r     *SA_ST + k0 + tig    ];
                af[mt][1] = cA[(r + 8)*SA_ST + k0 + tig    ];
                af[mt][2] = cA[ r     *SA_ST + k0 + tig + 4];
                af[mt][3] = cA[(r + 8)*SA_ST + k0 + tig + 4];
            }
            unsigned bf[4][2];
            #pragma unroll
            for (int nt = 0; nt < 4; nt++) {
                int c = wc*32 + nt*8 + gid;
                bf[nt][0] = cB[(k0 + tig    )*SB_ST + c];
                bf[nt][1] = cB[(k0 + tig + 4)*SB_ST + c];
            }
            #pragma unroll
            for (int mt = 0; mt < 2; mt++)
                #pragma unroll
                for (int nt = 0; nt < 4; nt++) {
                    asm volatile(
                      "mma.sync.aligned.m16n8k8.row.col.f32.tf32.tf32.f32 "
                      "{%0,%1,%2,%3},{%4,%5,%6,%7},{%8,%9},{%0,%1,%2,%3};"
                      : "+f"(acc[mt][nt][0]), "+f"(acc[mt][nt][1]),
                        "+f"(acc[mt][nt][2]), "+f"(acc[mt][nt][3])
                      : "r"(af[mt][0]), "r"(af[mt][1]),
                        "r"(af[mt][2]), "r"(af[mt][3]),
                        "r"(bf[nt][0]), "r"(bf[nt][1]));
                }
        }
        if (it + 2 < nk) { issue_stage(it + 2); cp_commit(); }
    }

    // epilogue (float2 stores; all M values are even)
    #pragma unroll
    for (int mt = 0; mt < 2; mt++) {
        #pragma unroll
        for (int nt = 0; nt < 4; nt++) {
            int r0  = row0 + wr*32 + mt*16 + gid;
            int col = col0 + wc*32 + nt*8 + tig*2;
            if (col < M) {
                float2 bb = make_float2(0.f, 0.f);
                if (bias) bb = *(const float2*)&bias[col];
                #pragma unroll
                for (int half = 0; half < 2; half++) {
                    int row = r0 + half*8;
                    float2 vv;
                    vv.x = acc[mt][nt][half*2    ] + bb.x;
                    vv.y = acc[mt][nt][half*2 + 1] + bb.y;
                    if (EPI == 1) {
                        vv.x = 0.5f * vv.x * (1.0f + erff(vv.x * 0.70710678118654752f));
                        vv.y = 0.5f * vv.y * (1.0f + erff(vv.y * 0.70710678118654752f));
                    } else if (EPI == 2) {
                        float2 rr = *(const float2*)&res[(size_t)row * M + col];
                        vv.x += rr.x; vv.y += rr.y;
                    }
                    *(float2*)&out[(size_t)row * M + col] = vv;
                }
            }
        }
    }
}

// ---------------- fused outlook attention + fold, head-coarsened ----------------
// warp = one token; loop over 6 heads. Window index math computed once.
__global__ void attn_fold_kernel(const float* __restrict__ a,
                                 const float* __restrict__ v,
                                 float* __restrict__ tmp)
{
    __shared__ float probs[8][ACOLS + 2];   // per-warp: [head][i][j]
    int warp = threadIdx.x >> 5;
    int lane = threadIdx.x & 31;
    int t = blockIdx.x * 8 + warp;
    int b  = t / (HH*WW);
    int pq = t % (HH*WW);
    int p = pq / WW, q = pq % WW;

    // ---- phase A: 54 softmax rows distributed over 27 lanes (2 each) ----
    if (lane < 27) {
        #pragma unroll
        for (int rep = 0; rep < 2; rep++) {
            int rr = lane + rep*27;            // 0..53
            int head = rr / K2;
            int i    = rr - head*K2;
            int di = i / KW, dj = i - di*KW;
            int tp = p + 1 - di, tq = q + 1 - dj;
            float* dst = &probs[warp][head*81 + i*K2];
            if ((unsigned)tp < (unsigned)HH && (unsigned)tq < (unsigned)WW) {
                int ts = (b*HH + tp) * WW + tq;
                const float* ar = a + (size_t)ts * ACOLS + head*81 + i*K2;
                float vv[K2];
                float mx = -INFINITY;
                #pragma unroll
                for (int j = 0; j < K2; j++) { vv[j] = ar[j] * SCALE; mx = fmaxf(mx, vv[j]); }
                float s = 0.f;
                #pragma unroll
                for (int j = 0; j < K2; j++) { vv[j] = __expf(vv[j] - mx); s += vv[j]; }
                float inv = __fdividef(1.f, s);
                #pragma unroll
                for (int j = 0; j < K2; j++) dst[j] = vv[j] * inv;
            } else {
                #pragma unroll
                for (int j = 0; j < K2; j++) dst[j] = 0.f;
            }
        }
    }
    __syncwarp();

    // ---- phase B: window gather, separable index precompute ----
    int rowbase[5], coloff[5];
    unsigned rmask = 0, cmask = 0;
    #pragma unroll
    for (int d = 0; d < 5; d++) {
        int vp = p + d - 2, vq = q + d - 2;
        bool rok = (unsigned)vp < (unsigned)HH;
        bool cok = (unsigned)vq < (unsigned)WW;
        rowbase[d] = rok ? ((b*HH + vp) * WW) * CC : 0;
        coloff[d]  = cok ? vq * CC : 0;
        if (rok) rmask |= (1u << d);
        if (cok) cmask |= (1u << d);
    }

    for (int head = 0; head < HEADS; head++) {
        const int ch = head*HD + lane;
        float vr[25];
        #pragma unroll
        for (int dp = 0; dp < 5; dp++) {
            #pragma unroll
            for (int dq = 0; dq < 5; dq++) {
                bool ok = ((rmask >> dp) & 1u) && ((cmask >> dq) & 1u);
                vr[dp*5 + dq] = ok ? v[(size_t)(rowbase[dp] + coloff[dq] + ch)] : 0.f;
            }
        }
        const float* pr = &probs[warp][head*81];
        float acc = 0.f;
        #pragma unroll
        for (int i = 0; i < K2; i++) {
            int di = i / KW, dj = i - di*KW;
            #pragma unroll
            for (int j = 0; j < K2; j++) {
                int ei = j / KW, ej = j - ei*KW;
                acc = fmaf(pr[i*K2 + j], vr[(ei - di + 2)*5 + (ej - dj + 2)], acc);
            }
        }
        tmp[(size_t)t * CC + ch] = acc;
    }
}

// ---------------- launcher ----------------
extern "C" void kernel_launch(void* const* d_in, const int* in_sizes, int n_in,
                              void* d_out, int out_size)
{
    const float* x     = (const float*)d_in[0];
    const float* ln1_g = (const float*)d_in[1];
    const float* ln1_b = (const float*)d_in[2];
    const float* Wv    = (const float*)d_in[3];
    const float* Wa    = (const float*)d_in[4];
    const float* ba    = (const float*)d_in[5];
    const float* Wp    = (const float*)d_in[6];
    const float* bp    = (const float*)d_in[7];
    const float* ln2_g = (const float*)d_in[8];
    const float* ln2_b = (const float*)d_in[9];
    const float* W1    = (const float*)d_in[10];
    const float* b1    = (const float*)d_in[11];
    const float* W2    = (const float*)d_in[12];
    const float* b2    = (const float*)d_in[13];
    float* out = (float*)d_out;

    float *p_ln1, *p_v, *p_a, *p_tmp, *p_x2, *p_ln2, *p_h1;
    cudaGetSymbolAddress((void**)&p_ln1, g_ln1);
    cudaGetSymbolAddress((void**)&p_v,   g_v);
    cudaGetSymbolAddress((void**)&p_a,   g_a);
    cudaGetSymbolAddress((void**)&p_tmp, g_tmp);
    cudaGetSymbolAddress((void**)&p_x2,  g_x2);
    cudaGetSymbolAddress((void**)&p_ln2, g_ln2);
    cudaGetSymbolAddress((void**)&p_h1,  g_h1);

    cudaFuncSetAttribute(gemm_tf32_kernel<0>, cudaFuncAttributeMaxDynamicSharedMemorySize, GEMM_SMEM);
    cudaFuncSetAttribute(gemm_tf32_kernel<1>, cudaFuncAttributeMaxDynamicSharedMemorySize, GEMM_SMEM);
    cudaFuncSetAttribute(gemm_tf32_kernel<2>, cudaFuncAttributeMaxDynamicSharedMemorySize, GEMM_SMEM);

    const int RB = NTOK / 128;   // 196

    ln_kernel<<<NTOK/8, 256>>>(x, ln1_g, ln1_b, p_ln1);
    gemm_tf32_kernel<0><<<dim3((CC+63)/64, RB), 256, GEMM_SMEM>>>(p_ln1, Wv, nullptr, nullptr, p_v, CC, CC);
    gemm_tf32_kernel<0><<<dim3((ACOLS+63)/64, RB), 256, GEMM_SMEM>>>(p_ln1, Wa, ba, nullptr, p_a, CC, ACOLS);
    attn_fold_kernel<<<NTOK/8, 256>>>(p_a, p_v, p_tmp);
    gemm_tf32_kernel<2><<<dim3((CC+63)/64, RB), 256, GEMM_SMEM>>>(p_tmp, Wp, bp, x, p_x2, CC, CC);
    ln_kernel<<<NTOK/8, 256>>>(p_x2, ln2_g, ln2_b, p_ln2);
    gemm_tf32_kernel<1><<<dim3((HID+63)/64, RB), 256, GEMM_SMEM>>>(p_ln2, W1, b1, nullptr, p_h1, CC, HID);
    gemm_tf32_kernel<2><<<dim3((CC+63)/64, RB), 256, GEMM_SMEM>>>(p_h1, W2, b2, p_x2, out, HID, CC);
}

// round 6
// speedup vs baseline: 4.2999x; 1.1286x over previous
#include <cuda_runtime.h>
#include <cuda_bf16.h>
#include <math.h>

// ---------------- problem constants ----------------
#define BB    32
#define HH    28
#define WW    28
#define CC    192
#define HEADS 6
#define HD    32
#define KW    3
#define K2    9
#define NTOK  (BB*HH*WW)          // 25088
#define HID   576
#define ACOLS (K2*K2*HEADS)       // 486
#define SCALE 0.17677669529663687f
#define EPSLN 1e-5f

// ---------------- scratch (static device globals; no allocs) ----------------
__device__ float g_ln1[(size_t)NTOK*CC];
__device__ float g_v  [(size_t)NTOK*CC];
__device__ float g_a  [(size_t)NTOK*ACOLS];
__device__ float g_tmp[(size_t)NTOK*CC];
__device__ float g_x2 [(size_t)NTOK*CC];
__device__ float g_ln2[(size_t)NTOK*CC];
__device__ float g_h1 [(size_t)NTOK*HID];

// ---------------- LayerNorm: one warp per token ----------------
__global__ void ln_kernel(const float* __restrict__ x,
                          const float* __restrict__ g,
                          const float* __restrict__ b,
                          float* __restrict__ out)
{
    int warp = (blockIdx.x * blockDim.x + threadIdx.x) >> 5;
    int lane = threadIdx.x & 31;
    if (warp >= NTOK) return;
    const float* row = x + (size_t)warp * CC;
    float vals[6];
    float s = 0.f;
    #pragma unroll
    for (int i = 0; i < 6; i++) { vals[i] = row[lane + 32*i]; s += vals[i]; }
    #pragma unroll
    for (int o = 16; o > 0; o >>= 1) s += __shfl_xor_sync(0xffffffffu, s, o);
    float mean = s * (1.f/CC);
    float vs = 0.f;
    #pragma unroll
    for (int i = 0; i < 6; i++) { float d = vals[i]-mean; vs += d*d; }
    #pragma unroll
    for (int o = 16; o > 0; o >>= 1) vs += __shfl_xor_sync(0xffffffffu, vs, o);
    float r = rsqrtf(vs * (1.f/CC) + EPSLN);
    float* orow = out + (size_t)warp * CC;
    #pragma unroll
    for (int i = 0; i < 6; i++) {
        int c = lane + 32*i;
        orow[c] = (vals[i]-mean) * r * g[c] + b[c];
    }
}

// ---------------- TF32 tensor-core GEMM (cp.async, 2-stage, 256x64 tile) ----------------
#define SA_ST 36   // 36 % 32 == 4 -> conflict-free A fragment reads
#define SB_ST 72   // >= 64 cols, 72 % 32 == 8 -> conflict-free B fragment reads
#define SA_SZ (256*SA_ST)          // words per A stage
#define SB_SZ (32*SB_ST)           // words per B stage
#define STG_WORDS (SA_SZ + SB_SZ)  // 11520 words / stage
#define GEMM_SMEM (2*STG_WORDS*4)  // 92160 bytes

__device__ __forceinline__ void cp16(unsigned dst, const void* src) {
    asm volatile("cp.async.ca.shared.global [%0], [%1], 16;" :: "r"(dst), "l"(src));
}
__device__ __forceinline__ void cp8z(unsigned dst, const void* src, int nbytes) {
    asm volatile("cp.async.ca.shared.global [%0], [%1], 8, %2;" :: "r"(dst), "l"(src), "r"(nbytes));
}
__device__ __forceinline__ void cp_commit() {
    asm volatile("cp.async.commit_group;");
}

template<int EPI>
__global__ __launch_bounds__(256, 2)
void gemm_tf32_kernel(const float* __restrict__ A,
                      const float* __restrict__ Bw,
                      const float* __restrict__ bias,
                      const float* __restrict__ res,
                      float* __restrict__ out,
                      int Kd, int M)
{
    extern __shared__ unsigned smem[];
    const unsigned smem_base = (unsigned)__cvta_generic_to_shared(smem);

    const int tid  = threadIdx.x;
    const int lane = tid & 31;
    const int w    = tid >> 5;
    const int wr   = w & 3;        // warp row group: 64 rows each
    const int wc   = w >> 2;       // warp col group: 32 cols each
    const int gid  = lane >> 2;
    const int tig  = lane & 3;
    const int row0 = blockIdx.y * 256;
    const int col0 = blockIdx.x * 64;

    float acc[4][4][4];
    #pragma unroll
    for (int mt = 0; mt < 4; mt++)
        #pragma unroll
        for (int nt = 0; nt < 4; nt++)
            #pragma unroll
            for (int i = 0; i < 4; i++) acc[mt][nt][i] = 0.f;

    const int nk = Kd / 32;

    auto issue_stage = [&](int s) {
        int kb = s * 32;
        unsigned base = smem_base + (unsigned)((s & 1) * STG_WORDS * 4);
        #pragma unroll
        for (int i = 0; i < 8; i++) {
            int f = tid + 256*i;
            int r = f >> 3, kq = (f & 7) * 4;
            cp16(base + (unsigned)((r*SA_ST + kq)*4),
                 &A[(size_t)(row0 + r) * Kd + kb + kq]);
        }
        unsigned bbase = base + (unsigned)(SA_SZ*4);
        #pragma unroll
        for (int i = 0; i < 4; i++) {
            int f = tid + 256*i;
            int kr = f >> 5, c2 = f & 31;
            int col = col0 + c2*2;
            int rem = M - col;
            int nb = rem >= 2 ? 8 : (rem == 1 ? 4 : 0);
            int colc = col < M - 2 ? col : M - 2;
            cp8z(bbase + (unsigned)((kr*SB_ST + c2*2)*4),
                 &Bw[(size_t)(kb + kr) * M + colc], nb);
        }
    };

    issue_stage(0); cp_commit();
    issue_stage(1); cp_commit();

    for (int it = 0; it < nk; it++) {
        if (it + 1 < nk) asm volatile("cp.async.wait_group 1;" ::: "memory");
        else             asm volatile("cp.async.wait_group 0;" ::: "memory");
        __syncthreads();

        const unsigned* cA = (const unsigned*)smem + (it & 1) * STG_WORDS;
        const unsigned* cB = cA + SA_SZ;
        #pragma unroll
        for (int ks = 0; ks < 4; ks++) {
            const int k0 = ks * 8;
            unsigned af[4][4];
            #pragma unroll
            for (int mt = 0; mt < 4; mt++) {
                int r = wr*64 + mt*16 + gid;
                af[mt][0] = cA[ r     *SA_ST + k0 + tig    ];
                af[mt][1] = cA[(r + 8)*SA_ST + k0 + tig    ];
                af[mt][2] = cA[ r     *SA_ST + k0 + tig + 4];
                af[mt][3] = cA[(r + 8)*SA_ST + k0 + tig + 4];
            }
            unsigned bf[4][2];
            #pragma unroll
            for (int nt = 0; nt < 4; nt++) {
                int c = wc*32 + nt*8 + gid;
                bf[nt][0] = cB[(k0 + tig    )*SB_ST + c];
                bf[nt][1] = cB[(k0 + tig + 4)*SB_ST + c];
            }
            #pragma unroll
            for (int mt = 0; mt < 4; mt++)
                #pragma unroll
                for (int nt = 0; nt < 4; nt++) {
                    asm volatile(
                      "mma.sync.aligned.m16n8k8.row.col.f32.tf32.tf32.f32 "
                      "{%0,%1,%2,%3},{%4,%5,%6,%7},{%8,%9},{%0,%1,%2,%3};"
                      : "+f"(acc[mt][nt][0]), "+f"(acc[mt][nt][1]),
                        "+f"(acc[mt][nt][2]), "+f"(acc[mt][nt][3])
                      : "r"(af[mt][0]), "r"(af[mt][1]),
                        "r"(af[mt][2]), "r"(af[mt][3]),
                        "r"(bf[nt][0]), "r"(bf[nt][1]));
                }
        }
        // all warps done reading this buffer before overwriting it
        __syncthreads();
        if (it + 2 < nk) { issue_stage(it + 2); cp_commit(); }
    }

    // epilogue (float2 stores; all M values are even)
    #pragma unroll
    for (int mt = 0; mt < 4; mt++) {
        #pragma unroll
        for (int nt = 0; nt < 4; nt++) {
            int r0  = row0 + wr*64 + mt*16 + gid;
            int col = col0 + wc*32 + nt*8 + tig*2;
            if (col < M) {
                float2 bb = make_float2(0.f, 0.f);
                if (bias) bb = *(const float2*)&bias[col];
                #pragma unroll
                for (int half = 0; half < 2; half++) {
                    int row = r0 + half*8;
                    float2 vv;
                    vv.x = acc[mt][nt][half*2    ] + bb.x;
                    vv.y = acc[mt][nt][half*2 + 1] + bb.y;
                    if (EPI == 1) {
                        vv.x = 0.5f * vv.x * (1.0f + erff(vv.x * 0.70710678118654752f));
                        vv.y = 0.5f * vv.y * (1.0f + erff(vv.y * 0.70710678118654752f));
                    } else if (EPI == 2) {
                        float2 rr = *(const float2*)&res[(size_t)row * M + col];
                        vv.x += rr.x; vv.y += rr.y;
                    }
                    *(float2*)&out[(size_t)row * M + col] = vv;
                }
            }
        }
    }
}

// ---------------- fused outlook attention + fold, head-coarsened ----------------
// warp = one token; loop over 6 heads. Probs padded to 12-float rows for LDS.128.
#define PR_ROW 12                      // padded row stride (16B aligned)
#define PR_HEAD (K2*PR_ROW)            // 108 floats per head
#define PR_WARP (HEADS*PR_HEAD)        // 648 floats per warp

__global__ void attn_fold_kernel(const float* __restrict__ a,
                                 const float* __restrict__ v,
                                 float* __restrict__ tmp)
{
    __shared__ float probs[8][PR_WARP];   // 648*4*8 = 20736 B
    int warp = threadIdx.x >> 5;
    int lane = threadIdx.x & 31;
    int t = blockIdx.x * 8 + warp;
    int b  = t / (HH*WW);
    int pq = t % (HH*WW);
    int p = pq / WW, q = pq % WW;

    // ---- phase A: 54 softmax rows over 27 lanes (2 each) ----
    if (lane < 27) {
        #pragma unroll
        for (int rep = 0; rep < 2; rep++) {
            int rr = lane + rep*27;            // 0..53
            int head = rr / K2;
            int i    = rr - head*K2;
            int di = i / KW, dj = i - di*KW;
            int tp = p + 1 - di, tq = q + 1 - dj;
            float* dst = &probs[warp][head*PR_HEAD + i*PR_ROW];
            if ((unsigned)tp < (unsigned)HH && (unsigned)tq < (unsigned)WW) {
                int ts = (b*HH + tp) * WW + tq;
                const float* ar = a + (size_t)ts * ACOLS + head*81 + i*K2;
                float vv[K2];
                float mx = -INFINITY;
                #pragma unroll
                for (int j = 0; j < K2; j++) { vv[j] = ar[j] * SCALE; mx = fmaxf(mx, vv[j]); }
                float s = 0.f;
                #pragma unroll
                for (int j = 0; j < K2; j++) { vv[j] = __expf(vv[j] - mx); s += vv[j]; }
                float inv = __fdividef(1.f, s);
                #pragma unroll
                for (int j = 0; j < K2; j++) dst[j] = vv[j] * inv;
            } else {
                #pragma unroll
                for (int j = 0; j < K2; j++) dst[j] = 0.f;
            }
        }
    }
    __syncwarp();

    // ---- phase B: window gather, separable index precompute ----
    int rowbase[5], coloff[5];
    unsigned rmask = 0, cmask = 0;
    #pragma unroll
    for (int d = 0; d < 5; d++) {
        int vp = p + d - 2, vq = q + d - 2;
        bool rok = (unsigned)vp < (unsigned)HH;
        bool cok = (unsigned)vq < (unsigned)WW;
        rowbase[d] = rok ? ((b*HH + vp) * WW) * CC : 0;
        coloff[d]  = cok ? vq * CC : 0;
        if (rok) rmask |= (1u << d);
        if (cok) cmask |= (1u << d);
    }

    for (int head = 0; head < HEADS; head++) {
        const int ch = head*HD + lane;
        float vr[25];
        #pragma unroll
        for (int dp = 0; dp < 5; dp++) {
            #pragma unroll
            for (int dq = 0; dq < 5; dq++) {
                bool ok = ((rmask >> dp) & 1u) && ((cmask >> dq) & 1u);
                vr[dp*5 + dq] = ok ? v[(size_t)(rowbase[dp] + coloff[dq] + ch)] : 0.f;
            }
        }
        const float* prh = &probs[warp][head*PR_HEAD];
        float acc = 0.f;
        #pragma unroll
        for (int i = 0; i < K2; i++) {
            int di = i / KW, dj = i - di*KW;
            const float4* rp = (const float4*)(prh + i*PR_ROW);
            float4 r0 = rp[0], r1 = rp[1];
            float  r2 = prh[i*PR_ROW + 8];
            float pr[K2] = {r0.x, r0.y, r0.z, r0.w, r1.x, r1.y, r1.z, r1.w, r2};
            const float* vb = &vr[(2 - di)*5 + (2 - dj)];
            #pragma unroll
            for (int j = 0; j < K2; j++) {
                int ei = j / KW, ej = j - ei*KW;
                acc = fmaf(pr[j], vb[ei*5 + ej], acc);
            }
        }
        tmp[(size_t)t * CC + ch] = acc;
    }
}

// ---------------- launcher ----------------
extern "C" void kernel_launch(void* const* d_in, const int* in_sizes, int n_in,
                              void* d_out, int out_size)
{
    const float* x     = (const float*)d_in[0];
    const float* ln1_g = (const float*)d_in[1];
    const float* ln1_b = (const float*)d_in[2];
    const float* Wv    = (const float*)d_in[3];
    const float* Wa    = (const float*)d_in[4];
    const float* ba    = (const float*)d_in[5];
    const float* Wp    = (const float*)d_in[6];
    const float* bp    = (const float*)d_in[7];
    const float* ln2_g = (const float*)d_in[8];
    const float* ln2_b = (const float*)d_in[9];
    const float* W1    = (const float*)d_in[10];
    const float* b1    = (const float*)d_in[11];
    const float* W2    = (const float*)d_in[12];
    const float* b2    = (const float*)d_in[13];
    float* out = (float*)d_out;

    float *p_ln1, *p_v, *p_a, *p_tmp, *p_x2, *p_ln2, *p_h1;
    cudaGetSymbolAddress((void**)&p_ln1, g_ln1);
    cudaGetSymbolAddress((void**)&p_v,   g_v);
    cudaGetSymbolAddress((void**)&p_a,   g_a);
    cudaGetSymbolAddress((void**)&p_tmp, g_tmp);
    cudaGetSymbolAddress((void**)&p_x2,  g_x2);
    cudaGetSymbolAddress((void**)&p_ln2, g_ln2);
    cudaGetSymbolAddress((void**)&p_h1,  g_h1);

    cudaFuncSetAttribute(gemm_tf32_kernel<0>, cudaFuncAttributeMaxDynamicSharedMemorySize, GEMM_SMEM);
    cudaFuncSetAttribute(gemm_tf32_kernel<1>, cudaFuncAttributeMaxDynamicSharedMemorySize, GEMM_SMEM);
    cudaFuncSetAttribute(gemm_tf32_kernel<2>, cudaFuncAttributeMaxDynamicSharedMemorySize, GEMM_SMEM);

    const int RB = NTOK / 256;   // 98

    ln_kernel<<<NTOK/8, 256>>>(x, ln1_g, ln1_b, p_ln1);
    gemm_tf32_kernel<0><<<dim3((CC+63)/64, RB), 256, GEMM_SMEM>>>(p_ln1, Wv, nullptr, nullptr, p_v, CC, CC);
    gemm_tf32_kernel<0><<<dim3((ACOLS+63)/64, RB), 256, GEMM_SMEM>>>(p_ln1, Wa, ba, nullptr, p_a, CC, ACOLS);
    attn_fold_kernel<<<NTOK/8, 256>>>(p_a, p_v, p_tmp);
    gemm_tf32_kernel<2><<<dim3((CC+63)/64, RB), 256, GEMM_SMEM>>>(p_tmp, Wp, bp, x, p_x2, CC, CC);
    ln_kernel<<<NTOK/8, 256>>>(p_x2, ln2_g, ln2_b, p_ln2);
    gemm_tf32_kernel<1><<<dim3((HID+63)/64, RB), 256, GEMM_SMEM>>>(p_ln2, W1, b1, nullptr, p_h1, CC, HID);
    gemm_tf32_kernel<2><<<dim3((CC+63)/64, RB), 256, GEMM_SMEM>>>(p_h1, W2, b2, p_x2, out, HID, CC);
}